// round 12
// baseline (speedup 1.0000x reference)
#include <cuda_runtime.h>

// Decoder: 8 batches of 32-segment piecewise-linear functions sampled at
// 196608 uniform points. Output [8, 196608] fp32 = 6.29MB (L2-resident).
// 384 CTAs x 256 threads (4096 px/block): half the prologues/dispatches of
// the 768-CTA variant. Warp-0 prologue (shuffle scan + ballot search +
// predicated STS publish); blocks classified 0/1/>=2 knot boundaries.

#define S_TOTAL 196608
#define NB 8
#define NSEG 32
#define NP1 33
#define THREADS 256
#define ITERS 4                                     // float4s per thread
#define PIX_PER_BLOCK (THREADS * ITERS * 4)         // 4096
#define BLOCKS_PER_BATCH (S_TOTAL / PIX_PER_BLOCK)  // 48
#define FULLMASK 0xffffffffu

__global__ __launch_bounds__(THREADS) void decoder_pwl_kernel(
    const float* __restrict__ segx,
    const float* __restrict__ segy,
    float* __restrict__ out)
{
    __shared__ float  sxs[NSEG];   // fixed knots (fallback table)
    __shared__ float  sys[NSEG];
    __shared__ float  srs[NSEG];
    __shared__ float4 sA;          // {c0x, c0y, c0r, -}
    __shared__ float4 sB;          // {xb(=c1x), c1y, c1r, nseg}

    const int b = blockIdx.x / BLOCKS_PER_BATCH;
    const int chunk = blockIdx.x - b * BLOCKS_PER_BATCH;
    const int tid = threadIdx.x;
    const int s_base = chunk * PIX_PER_BLOCK;
    const float inv = 1.0f / (float)S_TOTAL;        // <=1ulp vs IEEE div; tol 1e-3

    if (tid < 32) {
        const int lane = tid;
        // ---- Running-max scan over 33 knots (ties -> later entry wins) ----
        const float* px = segx + b * NP1;
        const float* py = segy + b * NP1;
        const float x0v = px[0];                     // uniform LDG, broadcast
        const float y0v = py[0];
        float xv = px[lane + 1];
        float yv = py[lane + 1];
        #pragma unroll
        for (int d = 1; d < 32; d <<= 1) {
            float ox = __shfl_up_sync(FULLMASK, xv, d);
            float oy = __shfl_up_sync(FULLMASK, yv, d);
            if (lane >= d && ox > xv) { xv = ox; yv = oy; }
        }
        if (x0v > xv) { xv = x0v; yv = y0v; }        // fold in knot 0 as prefix
        float xp = __shfl_up_sync(FULLMASK, xv, 1);  // lane l: knot X[l]
        float yp = __shfl_up_sync(FULLMASK, yv, 1);  // lane l: Y[l]
        if (lane == 0) { xp = x0v; yp = y0v; }
        float dd = xv - xp;
        if (dd == 0.0f) dd = 0.0001f;
        const float rs = (yv - yp) / dd;             // lane l: slope of seg l

        // Fallback tables (off the critical path; BAR drains these STS).
        sxs[lane] = xp;
        sys[lane] = yp;
        srs[lane] = rs;

        // ---- Ballot search for block's first & last pixel ----
        // X[] non-decreasing across lanes -> prefix mask; j = highest set bit,
        // clamped to 0 (mask==0 reproduces the below-first-knot clamp; bit31
        // reproduces the above-last-knot clamp).
        const float x_lo = (float)(s_base + 1) * inv;
        const float x_hi = (float)(s_base + PIX_PER_BLOCK) * inv;
        const unsigned mlo = __ballot_sync(FULLMASK, xp <= x_lo);
        const unsigned mhi = __ballot_sync(FULLMASK, xp <= x_hi);
        const int jl = max(31 - __clz(mlo), 0);
        const int jh = max(31 - __clz(mhi), 0);

        // Publish block record by predicated direct stores (no gathers).
        if (lane == jl) sA = make_float4(xp, yp, rs, 0.0f);
        if (lane == jh) sB = make_float4(xp, yp, rs, (float)(jh - jl));
    }
    __syncthreads();

    const float xbase = (float)(s_base + tid * 4 + 1) * inv;  // thread's pixel 0
    float4* out4 = reinterpret_cast<float4*>(out);
    const int obase = b * (S_TOTAL / 4) + (s_base >> 2) + tid;

    const float4 c0 = sA;                            // one LDS.128
    const float4 c1 = sB;                            // one LDS.128 (w = nseg)

    if (c1.w == 0.0f) {
        // Dominant case (~68%): whole block inside one segment -> 3 ops/px.
        #pragma unroll
        for (int i = 0; i < ITERS; i++) {
            float4 o;
            float* ov = &o.x;
            #pragma unroll
            for (int e = 0; e < 4; e++) {
                float xin = xbase + (float)(i * THREADS * 4 + e) * inv;
                ov[e] = fmaf(c0.z, xin - c0.x, c0.y); // same arith order as ref
            }
            out4[obase + i * THREADS] = o;
        }
    } else if (c1.w == 1.0f) {
        // One knot boundary (xb = c1.x) inside this block -> predicated select.
        const float xb = c1.x;
        #pragma unroll
        for (int i = 0; i < ITERS; i++) {
            float4 o;
            float* ov = &o.x;
            #pragma unroll
            for (int e = 0; e < 4; e++) {
                float xin = xbase + (float)(i * THREADS * 4 + e) * inv;
                bool hi = (xin >= xb);
                float cx = hi ? c1.x : c0.x;
                float cy = hi ? c1.y : c0.y;
                float cr = hi ? c1.z : c0.z;
                ov[e] = fmaf(cr, xin - cx, cy);
            }
            out4[obase + i * THREADS] = o;
        }
    } else {
        // Rare: multiple knots in block -> per-pixel binary search in smem.
        #pragma unroll
        for (int i = 0; i < ITERS; i++) {
            float4 o;
            float* ov = &o.x;
            #pragma unroll
            for (int e = 0; e < 4; e++) {
                float xin = xbase + (float)(i * THREADS * 4 + e) * inv;
                int j = 0;
                #pragma unroll
                for (int st = 16; st >= 1; st >>= 1) {
                    if (sxs[j + st] <= xin) j += st;
                }
                ov[e] = fmaf(srs[j], xin - sxs[j], sys[j]);
            }
            out4[obase + i * THREADS] = o;
        }
    }
}

extern "C" void kernel_launch(void* const* d_in, const int* in_sizes, int n_in,
                              void* d_out, int out_size) {
    const float* segx = (const float*)d_in[0];
    const float* segy = (const float*)d_in[1];
    float* out = (float*)d_out;

    const int blocks = NB * BLOCKS_PER_BATCH;        // 384
    decoder_pwl_kernel<<<blocks, THREADS>>>(segx, segy, out);
}

// round 13
// speedup vs baseline: 1.0047x; 1.0047x over previous
#include <cuda_runtime.h>

// Decoder: 8 batches of 32-segment piecewise-linear functions sampled at
// 196608 uniform points. Output [8, 196608] fp32 = 6.29MB (L2-resident).
// Champion shape: 768 CTAs x 256 threads. Warp-0 prologue (shuffle scan ->
// ballot search overlapped with fast-div slope -> predicated STS publish),
// three-way block classification: 0 boundaries (~84%, 3-op/px), 1 boundary
// (7-op/px), >=2 (rare, conditional smem table + binary search).

#define S_TOTAL 196608
#define NB 8
#define NSEG 32
#define NP1 33
#define THREADS 256
#define ITERS 2                                     // float4s per thread
#define PIX_PER_BLOCK (THREADS * ITERS * 4)         // 2048
#define BLOCKS_PER_BATCH (S_TOTAL / PIX_PER_BLOCK)  // 96
#define FULLMASK 0xffffffffu

__global__ __launch_bounds__(THREADS) void decoder_pwl_kernel(
    const float* __restrict__ segx,
    const float* __restrict__ segy,
    float* __restrict__ out)
{
    __shared__ float4 scf[NSEG];   // fallback table {x, y, r, -} (rare blocks)
    __shared__ float4 sA;          // {c0x, c0y, c0r, -}
    __shared__ float4 sB;          // {xb(=c1x), c1y, c1r, nseg}

    const int b = blockIdx.x / BLOCKS_PER_BATCH;
    const int chunk = blockIdx.x - b * BLOCKS_PER_BATCH;
    const int tid = threadIdx.x;
    const int s_base = chunk * PIX_PER_BLOCK;
    const float inv = 1.0f / (float)S_TOTAL;        // <=1ulp vs IEEE div; tol 1e-3

    if (tid < 32) {
        const int lane = tid;
        // ---- Running-max scan over 33 knots (ties -> later entry wins) ----
        const float* px = segx + b * NP1;
        const float* py = segy + b * NP1;
        const float x0v = px[0];                     // uniform LDG, broadcast
        const float y0v = py[0];
        float xv = px[lane + 1];
        float yv = py[lane + 1];
        #pragma unroll
        for (int d = 1; d < 32; d <<= 1) {
            float ox = __shfl_up_sync(FULLMASK, xv, d);
            float oy = __shfl_up_sync(FULLMASK, yv, d);
            if (lane >= d && ox > xv) { xv = ox; yv = oy; }
        }
        if (x0v > xv) { xv = x0v; yv = y0v; }        // fold in knot 0 as prefix
        float xp = __shfl_up_sync(FULLMASK, xv, 1);  // lane l: knot X[l]
        float yp = __shfl_up_sync(FULLMASK, yv, 1);  // lane l: Y[l]
        if (lane == 0) { xp = x0v; yp = y0v; }

        // ---- Ballot search (needs only xp) — overlaps with the divide ----
        // X[] non-decreasing across lanes -> prefix mask; j = highest set bit.
        // m|1 makes mask==0 give j=0 (below-first-knot clamp); bit31 gives
        // segment 31 (above-last-knot clamp).
        const float x_lo = (float)(s_base + 1) * inv;
        const float x_hi = (float)(s_base + PIX_PER_BLOCK) * inv;
        const unsigned mlo = __ballot_sync(FULLMASK, xp <= x_lo);
        const unsigned mhi = __ballot_sync(FULLMASK, xp <= x_hi);
        const int jl = 31 - __clz(mlo | 1u);
        const int jh = 31 - __clz(mhi | 1u);

        // Slope via fast reciprocal (relerr ~2^-22, tolerance is 1e-3).
        float dd = xv - xp;
        if (dd == 0.0f) dd = 0.0001f;
        const float rs = __fdividef(yv - yp, dd);    // lane l: slope of seg l

        // Publish block record by predicated direct stores (no gathers).
        if (lane == jl) sA = make_float4(xp, yp, rs, 0.0f);
        if (lane == jh) sB = make_float4(xp, yp, rs, (float)(jh - jl));

        // Fallback table only when >=2 boundaries land in this block (<1%).
        if (jh > jl + 1) scf[lane] = make_float4(xp, yp, rs, 0.0f);
    }
    __syncthreads();

    const float xbase = (float)(s_base + tid * 4 + 1) * inv;  // thread's pixel 0
    float4* out4 = reinterpret_cast<float4*>(out);
    const int obase = b * (S_TOTAL / 4) + (s_base >> 2) + tid;

    const float4 c0 = sA;                            // one LDS.128
    const float4 c1 = sB;                            // one LDS.128 (w = nseg)

    if (c1.w == 0.0f) {
        // Dominant case (~84%): whole block inside one segment -> 3 ops/px.
        #pragma unroll
        for (int i = 0; i < ITERS; i++) {
            float4 o;
            float* ov = &o.x;
            #pragma unroll
            for (int e = 0; e < 4; e++) {
                float xin = xbase + (float)(i * THREADS * 4 + e) * inv;
                ov[e] = fmaf(c0.z, xin - c0.x, c0.y); // same arith order as ref
            }
            out4[obase + i * THREADS] = o;
        }
    } else if (c1.w == 1.0f) {
        // One knot boundary (xb = c1.x) inside this block -> predicated select.
        const float xb = c1.x;
        #pragma unroll
        for (int i = 0; i < ITERS; i++) {
            float4 o;
            float* ov = &o.x;
            #pragma unroll
            for (int e = 0; e < 4; e++) {
                float xin = xbase + (float)(i * THREADS * 4 + e) * inv;
                bool hi = (xin >= xb);
                float cx = hi ? c1.x : c0.x;
                float cy = hi ? c1.y : c0.y;
                float cr = hi ? c1.z : c0.z;
                ov[e] = fmaf(cr, xin - cx, cy);
            }
            out4[obase + i * THREADS] = o;
        }
    } else {
        // Rare: multiple knots in block -> per-pixel binary search in smem.
        #pragma unroll
        for (int i = 0; i < ITERS; i++) {
            float4 o;
            float* ov = &o.x;
            #pragma unroll
            for (int e = 0; e < 4; e++) {
                float xin = xbase + (float)(i * THREADS * 4 + e) * inv;
                int j = 0;
                #pragma unroll
                for (int st = 16; st >= 1; st >>= 1) {
                    if (scf[j + st].x <= xin) j += st;
                }
                float4 c = scf[j];
                ov[e] = fmaf(c.z, xin - c.x, c.y);
            }
            out4[obase + i * THREADS] = o;
        }
    }
}

extern "C" void kernel_launch(void* const* d_in, const int* in_sizes, int n_in,
                              void* d_out, int out_size) {
    const float* segx = (const float*)d_in[0];
    const float* segy = (const float*)d_in[1];
    float* out = (float*)d_out;

    const int blocks = NB * BLOCKS_PER_BATCH;        // 768
    decoder_pwl_kernel<<<blocks, THREADS>>>(segx, segy, out);
}

// round 14
// speedup vs baseline: 1.0485x; 1.0437x over previous
#include <cuda_runtime.h>

// Decoder: 8 batches of 32-segment piecewise-linear functions sampled at
// 196608 uniform points. Output [8, 196608] fp32 = 6.29MB (L2-resident).
// Champion shape: 768 CTAs x 256 threads. Warp-0 prologue (shuffle scan ->
// ballot search overlapped with fast-div slope -> predicated STS publish).
// Hot loop in incremental form: one FFMA per pixel in the dominant
// single-segment case (~84% of blocks); 5 ops/px with one boundary; rare
// >=2-boundary blocks use a smem binary search.

#define S_TOTAL 196608
#define NB 8
#define NSEG 32
#define NP1 33
#define THREADS 256
#define ITERS 2                                     // float4s per thread
#define PIX_PER_BLOCK (THREADS * ITERS * 4)         // 2048
#define BLOCKS_PER_BATCH (S_TOTAL / PIX_PER_BLOCK)  // 96
#define FULLMASK 0xffffffffu

__global__ __launch_bounds__(THREADS) void decoder_pwl_kernel(
    const float* __restrict__ segx,
    const float* __restrict__ segy,
    float* __restrict__ out)
{
    __shared__ float4 scf[NSEG];   // fallback table {x, y, r, -} (rare blocks)
    __shared__ float4 sA;          // {c0x, c0y, c0r, -}
    __shared__ float4 sB;          // {xb(=c1x), c1y, c1r, nseg}

    const int b = blockIdx.x / BLOCKS_PER_BATCH;
    const int chunk = blockIdx.x - b * BLOCKS_PER_BATCH;
    const int tid = threadIdx.x;
    const int s_base = chunk * PIX_PER_BLOCK;
    const float inv = 1.0f / (float)S_TOTAL;        // <=1ulp vs IEEE div; tol 1e-3

    if (tid < 32) {
        const int lane = tid;
        // ---- Running-max scan over 33 knots (ties -> later entry wins) ----
        const float* px = segx + b * NP1;
        const float* py = segy + b * NP1;
        const float x0v = px[0];                     // uniform LDG, broadcast
        const float y0v = py[0];
        float xv = px[lane + 1];
        float yv = py[lane + 1];
        #pragma unroll
        for (int d = 1; d < 32; d <<= 1) {
            float ox = __shfl_up_sync(FULLMASK, xv, d);
            float oy = __shfl_up_sync(FULLMASK, yv, d);
            if (lane >= d && ox > xv) { xv = ox; yv = oy; }
        }
        if (x0v > xv) { xv = x0v; yv = y0v; }        // fold in knot 0 as prefix
        float xp = __shfl_up_sync(FULLMASK, xv, 1);  // lane l: knot X[l]
        float yp = __shfl_up_sync(FULLMASK, yv, 1);  // lane l: Y[l]
        if (lane == 0) { xp = x0v; yp = y0v; }

        // ---- Ballot search (needs only xp) — overlaps with the divide ----
        // X[] non-decreasing across lanes -> prefix mask; j = highest set bit.
        // m|1 makes mask==0 give j=0 (below-first-knot clamp); bit31 gives
        // segment 31 (above-last-knot clamp).
        const float x_lo = (float)(s_base + 1) * inv;
        const float x_hi = (float)(s_base + PIX_PER_BLOCK) * inv;
        const unsigned mlo = __ballot_sync(FULLMASK, xp <= x_lo);
        const unsigned mhi = __ballot_sync(FULLMASK, xp <= x_hi);
        const int jl = 31 - __clz(mlo | 1u);
        const int jh = 31 - __clz(mhi | 1u);

        // Slope via fast reciprocal (relerr ~2^-22, tolerance is 1e-3).
        float dd = xv - xp;
        if (dd == 0.0f) dd = 0.0001f;
        const float rs = __fdividef(yv - yp, dd);    // lane l: slope of seg l

        // Publish block record by predicated direct stores (no gathers).
        if (lane == jl) sA = make_float4(xp, yp, rs, 0.0f);
        if (lane == jh) sB = make_float4(xp, yp, rs, (float)(jh - jl));

        // Fallback table only when >=2 boundaries land in this block (<1%).
        if (jh > jl + 1) scf[lane] = make_float4(xp, yp, rs, 0.0f);
    }
    __syncthreads();

    const float xbase = (float)(s_base + tid * 4 + 1) * inv;  // thread's pixel 0
    float4* out4 = reinterpret_cast<float4*>(out);
    const int obase = b * (S_TOTAL / 4) + (s_base >> 2) + tid;

    const float4 c0 = sA;                            // one LDS.128
    const float4 c1 = sB;                            // one LDS.128 (w = nseg)

    if (c1.w == 0.0f) {
        // Dominant case (~84%): one segment -> incremental form, 1 FFMA/px.
        // v(k) = v0 + k*dv, dv = slope*inv; added err <= k*ulp(dv) ~ 1e-8.
        const float v0 = fmaf(c0.z, xbase - c0.x, c0.y);
        const float dv = c0.z * inv;
        #pragma unroll
        for (int i = 0; i < ITERS; i++) {
            float4 o;
            float* ov = &o.x;
            #pragma unroll
            for (int e = 0; e < 4; e++) {
                ov[e] = fmaf((float)(i * THREADS * 4 + e), dv, v0);
            }
            out4[obase + i * THREADS] = o;
        }
    } else if (c1.w == 1.0f) {
        // One knot boundary (xb = c1.x): two incremental streams + select.
        const float xb  = c1.x;
        const float v0l = fmaf(c0.z, xbase - c0.x, c0.y);
        const float dvl = c0.z * inv;
        const float v0h = fmaf(c1.z, xbase - c1.x, c1.y);
        const float dvh = c1.z * inv;
        #pragma unroll
        for (int i = 0; i < ITERS; i++) {
            float4 o;
            float* ov = &o.x;
            #pragma unroll
            for (int e = 0; e < 4; e++) {
                const float k = (float)(i * THREADS * 4 + e);
                float xin = fmaf(k, inv, xbase);
                float vl = fmaf(k, dvl, v0l);
                float vh = fmaf(k, dvh, v0h);
                ov[e] = (xin >= xb) ? vh : vl;
            }
            out4[obase + i * THREADS] = o;
        }
    } else {
        // Rare: multiple knots in block -> per-pixel binary search in smem.
        #pragma unroll
        for (int i = 0; i < ITERS; i++) {
            float4 o;
            float* ov = &o.x;
            #pragma unroll
            for (int e = 0; e < 4; e++) {
                float xin = xbase + (float)(i * THREADS * 4 + e) * inv;
                int j = 0;
                #pragma unroll
                for (int st = 16; st >= 1; st >>= 1) {
                    if (scf[j + st].x <= xin) j += st;
                }
                float4 c = scf[j];
                ov[e] = fmaf(c.z, xin - c.x, c.y);
            }
            out4[obase + i * THREADS] = o;
        }
    }
}

extern "C" void kernel_launch(void* const* d_in, const int* in_sizes, int n_in,
                              void* d_out, int out_size) {
    const float* segx = (const float*)d_in[0];
    const float* segy = (const float*)d_in[1];
    float* out = (float*)d_out;

    const int blocks = NB * BLOCKS_PER_BATCH;        // 768
    decoder_pwl_kernel<<<blocks, THREADS>>>(segx, segy, out);
}